// round 1
// baseline (speedup 1.0000x reference)
#include <cuda_runtime.h>
#include <cmath>

// Problem constants
static constexpr int B_  = 2;
static constexpr int S_  = 2048;
static constexpr int D_  = 2048;
static constexpr int H_  = 16;
static constexpr int HD_ = 128;
static constexpr int ND_ = 64;
static constexpr int R_  = 512;
static constexpr int M_  = B_ * S_;   // 4096 total rows

// ---------------------------------------------------------------------------
// Scratch (device globals; allocation-free per harness rules)
// ---------------------------------------------------------------------------
__device__ float g_q  [M_ * D_];        // q projection, rope applied in-place
__device__ float g_ckv[M_ * R_];        // kv down-projection
__device__ float g_kn [M_ * H_ * ND_];  // k_nope
__device__ float g_kr [M_ * ND_];       // k_rope (shared across heads)
__device__ float g_v  [M_ * D_];        // v
__device__ float g_ao [M_ * D_];        // attention output (pre-wo)
__device__ float g_cos[S_ * 32];
__device__ float g_sin[S_ * 32];

// ---------------------------------------------------------------------------
// RoPE table: freqs/angles in fp64, then cos/sin (matches fp32 jax ref ~1e-7)
// ---------------------------------------------------------------------------
__global__ void build_rope_table() {
    int idx = blockIdx.x * blockDim.x + threadIdx.x;
    if (idx >= S_ * 32) return;
    int i   = idx & 31;
    int pos = idx >> 5;
    double freq = 1.0 / pow(10000.0, (2.0 * i) / 64.0);
    double ang  = (double)pos * freq;
    g_cos[idx] = (float)cos(ang);
    g_sin[idx] = (float)sin(ang);
}

// RoPE on q: last 64 dims of each head. Interleaved convention:
// out[2i] = x[2i]*c - x[2i+1]*s ;  out[2i+1] = x[2i+1]*c + x[2i]*s
__global__ void rope_q_kernel() {
    int idx = blockIdx.x * blockDim.x + threadIdx.x;
    if (idx >= M_ * H_ * 32) return;
    int i   = idx & 31;
    int h   = (idx >> 5) & (H_ - 1);
    int row = idx >> 9;
    int pos = row & (S_ - 1);
    float c  = g_cos[pos * 32 + i];
    float sn = g_sin[pos * 32 + i];
    float2* p = (float2*)(g_q + (size_t)row * D_ + h * HD_ + ND_ + 2 * i);
    float2 x = *p;
    float2 y;
    y.x = x.x * c - x.y * sn;
    y.y = x.y * c + x.x * sn;
    *p = y;
}

__global__ void rope_k_kernel() {
    int idx = blockIdx.x * blockDim.x + threadIdx.x;
    if (idx >= M_ * 32) return;
    int i   = idx & 31;
    int row = idx >> 5;
    int pos = row & (S_ - 1);
    float c  = g_cos[pos * 32 + i];
    float sn = g_sin[pos * 32 + i];
    float2* p = (float2*)(g_kr + (size_t)row * ND_ + 2 * i);
    float2 x = *p;
    float2 y;
    y.x = x.x * c - x.y * sn;
    y.y = x.y * c + x.x * sn;
    *p = y;
}

// ---------------------------------------------------------------------------
// Generic fp32 NT GEMM: C[M,N] = A[M,K] @ Bw[N,K]^T  (both row-major)
// 128x128 block tile, BK=8, 256 threads, 8x8 microtile per thread.
// M assumed multiple of 128 (always 4096). N guarded (N=64 case).
// ---------------------------------------------------------------------------
__global__ __launch_bounds__(256)
void sgemm_nt(const float* __restrict__ A, const float* __restrict__ Bw,
              float* __restrict__ C, int M, int N, int K) {
    __shared__ float sA[8][128];
    __shared__ float sB[8][128];

    const int tid = threadIdx.x;
    const int m0 = blockIdx.y * 128;
    const int n0 = blockIdx.x * 128;
    const int ty = tid >> 4, tx = tid & 15;   // 16x16 thread grid
    const int lrow = tid >> 1;                // 0..127
    const int lcol = (tid & 1) * 4;           // 0 or 4

    float acc[8][8];
#pragma unroll
    for (int i = 0; i < 8; i++)
#pragma unroll
        for (int j = 0; j < 8; j++) acc[i][j] = 0.f;

    for (int k0 = 0; k0 < K; k0 += 8) {
        float4 av = *(const float4*)&A[(m0 + lrow) * K + k0 + lcol];
        float4 bv = make_float4(0.f, 0.f, 0.f, 0.f);
        int brow = n0 + lrow;
        if (brow < N) bv = *(const float4*)&Bw[brow * K + k0 + lcol];
        __syncthreads();
        sA[lcol + 0][lrow] = av.x;
        sA[lcol + 1][lrow] = av.y;
        sA[lcol + 2][lrow] = av.z;
        sA[lcol + 3][lrow] = av.w;
        sB[lcol + 0][lrow] = bv.x;
        sB[lcol + 1][lrow] = bv.y;
        sB[lcol + 2][lrow] = bv.z;
        sB[lcol + 3][lrow] = bv.w;
        __syncthreads();
#pragma unroll
        for (int kk = 0; kk < 8; kk++) {
            float a[8], b[8];
            *(float4*)(a)     = *(const float4*)&sA[kk][ty * 8];
            *(float4*)(a + 4) = *(const float4*)&sA[kk][ty * 8 + 4];
            *(float4*)(b)     = *(const float4*)&sB[kk][tx * 8];
            *(float4*)(b + 4) = *(const float4*)&sB[kk][tx * 8 + 4];
#pragma unroll
            for (int i = 0; i < 8; i++)
#pragma unroll
                for (int j = 0; j < 8; j++) acc[i][j] += a[i] * b[j];
        }
    }

#pragma unroll
    for (int i = 0; i < 8; i++) {
        int m = m0 + ty * 8 + i;
#pragma unroll
        for (int j = 0; j < 8; j++) {
            int n = n0 + tx * 8 + j;
            if (n < N) C[m * N + n] = acc[i][j];
        }
    }
}

// ---------------------------------------------------------------------------
// Flash attention (fp32, causal). Effective 128-dim K = [k_nope_h | k_rope].
// Grid: (S/64 q-tiles, H, B). Block: 256 threads.
// BQ=64, BK=64. Q tile resident in smem (pre-scaled), K^T padded/transposed.
// ---------------------------------------------------------------------------
static constexpr int BQ = 64, BKt = 64, DH = 128, KPAD = 68, SPAD = 68;
static constexpr int FLASH_SMEM =
    (BQ * DH + DH * KPAD + BKt * DH + BQ * SPAD + 3 * BQ) * 4;  // 118528 B

__global__ __launch_bounds__(256)
void flash_kernel() {
    extern __shared__ float sh[];
    float* sQ  = sh;                   // [64][128]
    float* sKT = sQ + BQ * DH;         // [128][KPAD]
    float* sV  = sKT + DH * KPAD;      // [64][128]
    float* sS  = sV + BKt * DH;        // [64][SPAD]
    float* sM  = sS + BQ * SPAD;
    float* sL  = sM + BQ;
    float* sAl = sL + BQ;

    const int qt = blockIdx.x, h = blockIdx.y, b = blockIdx.z;
    const int tid = threadIdx.x;
    const int ty = tid >> 4, tx = tid & 15;
    const int q0 = qt * BQ;
    const int rowb = b * S_;
    const float scale = 0.08838834764831845f;  // 1/sqrt(128)

    // Load Q tile (pre-scaled)
    for (int e = tid; e < BQ * DH; e += 256) {
        int r = e >> 7, d = e & 127;
        sQ[e] = g_q[(rowb + q0 + r) * D_ + h * HD_ + d] * scale;
    }
    if (tid < BQ) { sM[tid] = -1e30f; sL[tid] = 0.f; }

    float accO[4][8];
#pragma unroll
    for (int i = 0; i < 4; i++)
#pragma unroll
        for (int j = 0; j < 8; j++) accO[i][j] = 0.f;

    for (int kt = 0; kt <= qt; kt++) {
        const int k0 = kt * BKt;
        __syncthreads();  // protect smem from previous iteration readers

        // Load K^T (transposed, padded) and V
        for (int e = tid; e < BKt * DH; e += 256) {
            int c = e >> 7, d = e & 127;
            float kv = (d < 64)
                ? g_kn[(rowb + k0 + c) * (H_ * ND_) + h * ND_ + d]
                : g_kr[(rowb + k0 + c) * ND_ + (d - 64)];
            sKT[d * KPAD + c] = kv;
            sV[e] = g_v[(rowb + k0 + c) * D_ + h * HD_ + d];
        }
        __syncthreads();

        // S = Q K^T : each thread 4x4 of a 64x64 tile
        float accS[4][4];
#pragma unroll
        for (int i = 0; i < 4; i++)
#pragma unroll
            for (int j = 0; j < 4; j++) accS[i][j] = 0.f;

        const float* qr = sQ + (ty * 4) * DH;
#pragma unroll 4
        for (int d = 0; d < DH; d++) {
            float a0 = qr[d];
            float a1 = qr[DH + d];
            float a2 = qr[2 * DH + d];
            float a3 = qr[3 * DH + d];
            float4 bv = *(const float4*)&sKT[d * KPAD + tx * 4];
            accS[0][0] += a0 * bv.x; accS[0][1] += a0 * bv.y;
            accS[0][2] += a0 * bv.z; accS[0][3] += a0 * bv.w;
            accS[1][0] += a1 * bv.x; accS[1][1] += a1 * bv.y;
            accS[1][2] += a1 * bv.z; accS[1][3] += a1 * bv.w;
            accS[2][0] += a2 * bv.x; accS[2][1] += a2 * bv.y;
            accS[2][2] += a2 * bv.z; accS[2][3] += a2 * bv.w;
            accS[3][0] += a3 * bv.x; accS[3][1] += a3 * bv.y;
            accS[3][2] += a3 * bv.z; accS[3][3] += a3 * bv.w;
        }

        // Causal mask + store scores
#pragma unroll
        for (int i = 0; i < 4; i++) {
            int qrow = q0 + ty * 4 + i;
#pragma unroll
            for (int j = 0; j < 4; j++) {
                int kcol = k0 + tx * 4 + j;
                sS[(ty * 4 + i) * SPAD + tx * 4 + j] =
                    (kcol <= qrow) ? accS[i][j] : -1e30f;
            }
        }
        __syncthreads();

        // Online softmax: 4 threads per row
        {
            int r = tid >> 2, l4 = tid & 3;
            float* srow = sS + r * SPAD;
            float mx = -1e30f;
            for (int c = l4; c < BKt; c += 4) mx = fmaxf(mx, srow[c]);
            mx = fmaxf(mx, __shfl_xor_sync(0xffffffffu, mx, 1));
            mx = fmaxf(mx, __shfl_xor_sync(0xffffffffu, mx, 2));
            float mold = sM[r];
            float mnew = fmaxf(mold, mx);
            float sum = 0.f;
            for (int c = l4; c < BKt; c += 4) {
                float p = __expf(srow[c] - mnew);
                srow[c] = p;
                sum += p;
            }
            sum += __shfl_xor_sync(0xffffffffu, sum, 1);
            sum += __shfl_xor_sync(0xffffffffu, sum, 2);
            if (l4 == 0) {
                sAl[r] = __expf(mold - mnew);
                sL[r]  = sL[r] * sAl[r] + sum;
                sM[r]  = mnew;
            }
        }
        __syncthreads();

        // Rescale O and accumulate P @ V
        float al[4];
#pragma unroll
        for (int i = 0; i < 4; i++) al[i] = sAl[ty * 4 + i];
#pragma unroll
        for (int i = 0; i < 4; i++)
#pragma unroll
            for (int j = 0; j < 8; j++) accO[i][j] *= al[i];

#pragma unroll 2
        for (int c = 0; c < BKt; c++) {
            float a0 = sS[(ty * 4 + 0) * SPAD + c];
            float a1 = sS[(ty * 4 + 1) * SPAD + c];
            float a2 = sS[(ty * 4 + 2) * SPAD + c];
            float a3 = sS[(ty * 4 + 3) * SPAD + c];
            float4 b0 = *(const float4*)&sV[c * DH + tx * 8];
            float4 b1 = *(const float4*)&sV[c * DH + tx * 8 + 4];
            accO[0][0] += a0 * b0.x; accO[0][1] += a0 * b0.y;
            accO[0][2] += a0 * b0.z; accO[0][3] += a0 * b0.w;
            accO[0][4] += a0 * b1.x; accO[0][5] += a0 * b1.y;
            accO[0][6] += a0 * b1.z; accO[0][7] += a0 * b1.w;
            accO[1][0] += a1 * b0.x; accO[1][1] += a1 * b0.y;
            accO[1][2] += a1 * b0.z; accO[1][3] += a1 * b0.w;
            accO[1][4] += a1 * b1.x; accO[1][5] += a1 * b1.y;
            accO[1][6] += a1 * b1.z; accO[1][7] += a1 * b1.w;
            accO[2][0] += a2 * b0.x; accO[2][1] += a2 * b0.y;
            accO[2][2] += a2 * b0.z; accO[2][3] += a2 * b0.w;
            accO[2][4] += a2 * b1.x; accO[2][5] += a2 * b1.y;
            accO[2][6] += a2 * b1.z; accO[2][7] += a2 * b1.w;
            accO[3][0] += a3 * b0.x; accO[3][1] += a3 * b0.y;
            accO[3][2] += a3 * b0.z; accO[3][3] += a3 * b0.w;
            accO[3][4] += a3 * b1.x; accO[3][5] += a3 * b1.y;
            accO[3][6] += a3 * b1.z; accO[3][7] += a3 * b1.w;
        }
    }

    // Epilogue: normalize and write
    float inv[4];
#pragma unroll
    for (int i = 0; i < 4; i++) inv[i] = 1.f / sL[ty * 4 + i];
#pragma unroll
    for (int i = 0; i < 4; i++) {
        int row = rowb + q0 + ty * 4 + i;
#pragma unroll
        for (int j = 0; j < 8; j++)
            g_ao[row * D_ + h * HD_ + tx * 8 + j] = accO[i][j] * inv[i];
    }
}

// ---------------------------------------------------------------------------
// Launch
// ---------------------------------------------------------------------------
extern "C" void kernel_launch(void* const* d_in, const int* in_sizes, int n_in,
                              void* d_out, int out_size) {
    const float* x    = (const float*)d_in[0];
    const float* wq   = (const float*)d_in[1];
    const float* wkvd = (const float*)d_in[2];
    const float* wkup = (const float*)d_in[3];
    const float* wkr  = (const float*)d_in[4];
    const float* wvup = (const float*)d_in[5];
    const float* wo   = (const float*)d_in[6];
    float* out = (float*)d_out;

    float *q_p, *ckv_p, *kn_p, *kr_p, *v_p, *ao_p;
    cudaGetSymbolAddress((void**)&q_p,   g_q);
    cudaGetSymbolAddress((void**)&ckv_p, g_ckv);
    cudaGetSymbolAddress((void**)&kn_p,  g_kn);
    cudaGetSymbolAddress((void**)&kr_p,  g_kr);
    cudaGetSymbolAddress((void**)&v_p,   g_v);
    cudaGetSymbolAddress((void**)&ao_p,  g_ao);

    cudaFuncSetAttribute(flash_kernel,
                         cudaFuncAttributeMaxDynamicSharedMemorySize,
                         FLASH_SMEM);

    build_rope_table<<<(S_ * 32 + 255) / 256, 256>>>();

    // Projections (all NT GEMMs)
    sgemm_nt<<<dim3(D_ / 128, M_ / 128), 256>>>(x, wq, q_p, M_, D_, D_);
    sgemm_nt<<<dim3(R_ / 128, M_ / 128), 256>>>(x, wkvd, ckv_p, M_, R_, D_);
    sgemm_nt<<<dim3((H_ * ND_) / 128, M_ / 128), 256>>>(ckv_p, wkup, kn_p, M_, H_ * ND_, R_);
    sgemm_nt<<<dim3(1, M_ / 128), 256>>>(x, wkr, kr_p, M_, ND_, D_);
    sgemm_nt<<<dim3(D_ / 128, M_ / 128), 256>>>(ckv_p, wvup, v_p, M_, D_, R_);

    // RoPE
    rope_q_kernel<<<(M_ * H_ * 32) / 256, 256>>>();
    rope_k_kernel<<<(M_ * 32) / 256, 256>>>();

    // Flash attention
    flash_kernel<<<dim3(S_ / BQ, H_, B_), 256, FLASH_SMEM>>>();

    // Output projection
    sgemm_nt<<<dim3(D_ / 128, M_ / 128), 256>>>(ao_p, wo, out, M_, D_, D_);
}

// round 4
// speedup vs baseline: 1.9581x; 1.9581x over previous
#include <cuda_runtime.h>
#include <cstdint>
#include <cmath>

// Problem constants
static constexpr int B_  = 2;
static constexpr int S_  = 2048;
static constexpr int D_  = 2048;
static constexpr int H_  = 16;
static constexpr int HD_ = 128;
static constexpr int ND_ = 64;
static constexpr int R_  = 512;
static constexpr int M_  = B_ * S_;   // 4096 total rows

// ---------------------------------------------------------------------------
// Scratch (device globals; allocation-free per harness rules)
// ---------------------------------------------------------------------------
__device__ float g_q  [M_ * D_];        // q projection, rope applied in-place
__device__ float g_ckv[M_ * R_];        // kv down-projection
__device__ float g_kn [M_ * H_ * ND_];  // k_nope
__device__ float g_kr [M_ * ND_];       // k_rope (shared across heads)
__device__ float g_v  [M_ * D_];        // v
__device__ float g_ao [M_ * D_];        // attention output (pre-wo)
__device__ float g_cos[S_ * 32];
__device__ float g_sin[S_ * 32];

// ---------------------------------------------------------------------------
// tf32 helpers
// ---------------------------------------------------------------------------
__device__ __forceinline__ float tf32r(float x) {
    uint32_t u;
    asm("cvt.rna.tf32.f32 %0, %1;" : "=r"(u) : "f"(x));
    return __uint_as_float(u);
}

__device__ __forceinline__ void mma8(float* c, const uint32_t* a, const uint32_t* b) {
    asm("mma.sync.aligned.m16n8k8.row.col.f32.tf32.tf32.f32 "
        "{%0,%1,%2,%3}, {%4,%5,%6,%7}, {%8,%9}, {%0,%1,%2,%3};"
        : "+f"(c[0]), "+f"(c[1]), "+f"(c[2]), "+f"(c[3])
        : "r"(a[0]), "r"(a[1]), "r"(a[2]), "r"(a[3]), "r"(b[0]), "r"(b[1]));
}

// ---------------------------------------------------------------------------
// RoPE table: freqs/angles in fp64, then cos/sin (matches fp32 jax ref ~1e-7)
// ---------------------------------------------------------------------------
__global__ void build_rope_table() {
    int idx = blockIdx.x * blockDim.x + threadIdx.x;
    if (idx >= S_ * 32) return;
    int i   = idx & 31;
    int pos = idx >> 5;
    double freq = 1.0 / pow(10000.0, (2.0 * i) / 64.0);
    double ang  = (double)pos * freq;
    g_cos[idx] = (float)cos(ang);
    g_sin[idx] = (float)sin(ang);
}

__global__ void rope_q_kernel() {
    int idx = blockIdx.x * blockDim.x + threadIdx.x;
    if (idx >= M_ * H_ * 32) return;
    int i   = idx & 31;
    int h   = (idx >> 5) & (H_ - 1);
    int row = idx >> 9;
    int pos = row & (S_ - 1);
    float c  = g_cos[pos * 32 + i];
    float sn = g_sin[pos * 32 + i];
    float2* p = (float2*)(g_q + (size_t)row * D_ + h * HD_ + ND_ + 2 * i);
    float2 x = *p;
    float2 y;
    y.x = x.x * c - x.y * sn;
    y.y = x.y * c + x.x * sn;
    *p = y;
}

__global__ void rope_k_kernel() {
    int idx = blockIdx.x * blockDim.x + threadIdx.x;
    if (idx >= M_ * 32) return;
    int i   = idx & 31;
    int row = idx >> 5;
    int pos = row & (S_ - 1);
    float c  = g_cos[pos * 32 + i];
    float sn = g_sin[pos * 32 + i];
    float2* p = (float2*)(g_kr + (size_t)row * ND_ + 2 * i);
    float2 x = *p;
    float2 y;
    y.x = x.x * c - x.y * sn;
    y.y = x.y * c + x.x * sn;
    *p = y;
}

// ---------------------------------------------------------------------------
// tf32 tensor-core NT GEMM: C[M,N] = A[M,K] @ Bw[N,K]^T  (both row-major)
// Block tile 128x128, BK=32, 8 warps (4m x 2n), warp tile 32x64.
// Smem stride 36 (== 4 mod 32): conflict-free fragment loads.
// ---------------------------------------------------------------------------
__global__ __launch_bounds__(256)
void tgemm_nt(const float* __restrict__ A, const float* __restrict__ Bw,
              float* __restrict__ C, int M, int N, int K) {
    __shared__ float sA[128][36];
    __shared__ float sB[128][36];

    const int tid  = threadIdx.x;
    const int wid  = tid >> 5, lane = tid & 31;
    const int grp  = lane >> 2, tig = lane & 3;
    const int wm   = wid >> 1, wn = wid & 1;      // 4 x 2 warp grid
    const int m0   = blockIdx.y * 128;
    const int n0   = blockIdx.x * 128;
    const int lr   = tid >> 3;                    // 0..31
    const int lc   = (tid & 7) * 4;               // 0..28 step 4

    float c[2][8][4];
#pragma unroll
    for (int i = 0; i < 2; i++)
#pragma unroll
        for (int j = 0; j < 8; j++)
#pragma unroll
            for (int t = 0; t < 4; t++) c[i][j][t] = 0.f;

    for (int k0 = 0; k0 < K; k0 += 32) {
        __syncthreads();
#pragma unroll
        for (int p = 0; p < 4; p++) {
            int r = lr + p * 32;
            float4 av = *(const float4*)&A[(size_t)(m0 + r) * K + k0 + lc];
            sA[r][lc + 0] = tf32r(av.x);
            sA[r][lc + 1] = tf32r(av.y);
            sA[r][lc + 2] = tf32r(av.z);
            sA[r][lc + 3] = tf32r(av.w);
            float4 bv = make_float4(0.f, 0.f, 0.f, 0.f);
            if (n0 + r < N) bv = *(const float4*)&Bw[(size_t)(n0 + r) * K + k0 + lc];
            sB[r][lc + 0] = tf32r(bv.x);
            sB[r][lc + 1] = tf32r(bv.y);
            sB[r][lc + 2] = tf32r(bv.z);
            sB[r][lc + 3] = tf32r(bv.w);
        }
        __syncthreads();

#pragma unroll
        for (int ks = 0; ks < 4; ks++) {
            const int kb = ks * 8;
            uint32_t a[2][4];
#pragma unroll
            for (int i = 0; i < 2; i++) {
                int row = wm * 32 + i * 16;
                a[i][0] = __float_as_uint(sA[row + grp    ][kb + tig]);
                a[i][1] = __float_as_uint(sA[row + grp + 8][kb + tig]);
                a[i][2] = __float_as_uint(sA[row + grp    ][kb + tig + 4]);
                a[i][3] = __float_as_uint(sA[row + grp + 8][kb + tig + 4]);
            }
#pragma unroll
            for (int j = 0; j < 8; j++) {
                int col = wn * 64 + j * 8;
                uint32_t b[2];
                b[0] = __float_as_uint(sB[col + grp][kb + tig]);
                b[1] = __float_as_uint(sB[col + grp][kb + tig + 4]);
                mma8(c[0][j], a[0], b);
                mma8(c[1][j], a[1], b);
            }
        }
    }

#pragma unroll
    for (int i = 0; i < 2; i++) {
        int m1 = m0 + wm * 32 + i * 16 + grp;
        int m2 = m1 + 8;
#pragma unroll
        for (int j = 0; j < 8; j++) {
            int n = n0 + wn * 64 + j * 8 + tig * 2;
            if (n < N) {
                *(float2*)&C[(size_t)m1 * N + n] = make_float2(c[i][j][0], c[i][j][1]);
                *(float2*)&C[(size_t)m2 * N + n] = make_float2(c[i][j][2], c[i][j][3]);
            }
        }
    }
}

// ---------------------------------------------------------------------------
// Flash attention (causal), tf32 tensor cores for QK^T and PV.
// BQ=64, BK=64, D=128. 256 threads (8 warps).
// S phase: warp grid 4m x 2n over 64x64 (warp tile 16x32).
// PV phase: warp grid 4m x 2n over 64x128 (warp tile 16x64).
// ---------------------------------------------------------------------------
static constexpr int QP = 132, KP = 132, VP = 68, SP = 68;
static constexpr int FLASH_SMEM =
    (64 * QP + 64 * KP + 128 * VP + 64 * SP + 3 * 64) * 4;  // 120576 B

__global__ __launch_bounds__(256)
void flash_kernel() {
    extern __shared__ float sh[];
    float* sQ  = sh;                   // [64][132] tf32-rounded, pre-scaled
    float* sK  = sQ + 64 * QP;         // [64][132] tf32-rounded
    float* sVT = sK + 64 * KP;         // [128][68] V transposed, tf32-rounded
    float* sS  = sVT + 128 * VP;       // [64][68]
    float* sM  = sS + 64 * SP;
    float* sL  = sM + 64;
    float* sAl = sL + 64;

    const int qt = blockIdx.x, h = blockIdx.y, b = blockIdx.z;
    const int tid = threadIdx.x;
    const int wid = tid >> 5, lane = tid & 31;
    const int grp = lane >> 2, tig = lane & 3;
    const int wm = wid >> 1, wn = wid & 1;
    const int q0 = qt * 64;
    const int rowb = b * S_;
    const float scale = 0.08838834764831845f;  // 1/sqrt(128)

    // Load Q tile (pre-scaled, tf32-rounded)
    for (int e = tid; e < 64 * 128; e += 256) {
        int r = e >> 7, d = e & 127;
        sQ[r * QP + d] = tf32r(g_q[(size_t)(rowb + q0 + r) * D_ + h * HD_ + d] * scale);
    }
    if (tid < 64) { sM[tid] = -1e30f; sL[tid] = 0.f; }

    float of[8][4];
#pragma unroll
    for (int j = 0; j < 8; j++)
#pragma unroll
        for (int t = 0; t < 4; t++) of[j][t] = 0.f;

    for (int kt = 0; kt <= qt; kt++) {
        const int k0 = kt * 64;
        __syncthreads();  // protect smem from previous iteration readers

        // Load K (concat k_nope|k_rope) and V transposed
        for (int e = tid; e < 64 * 128; e += 256) {
            int c = e >> 7, d = e & 127;
            float kv = (d < 64)
                ? g_kn[(size_t)(rowb + k0 + c) * (H_ * ND_) + h * ND_ + d]
                : g_kr[(size_t)(rowb + k0 + c) * ND_ + (d - 64)];
            sK[c * KP + d] = tf32r(kv);
            sVT[d * VP + c] = tf32r(g_v[(size_t)(rowb + k0 + c) * D_ + h * HD_ + d]);
        }
        __syncthreads();

        // S = Q K^T via mma (16 k-steps of 8 over D=128)
        float sf[4][4];
#pragma unroll
        for (int j = 0; j < 4; j++)
#pragma unroll
            for (int t = 0; t < 4; t++) sf[j][t] = 0.f;

#pragma unroll
        for (int ks = 0; ks < 16; ks++) {
            const int kb = ks * 8;
            uint32_t a[4];
            const int row = wm * 16;
            a[0] = __float_as_uint(sQ[(row + grp    ) * QP + kb + tig]);
            a[1] = __float_as_uint(sQ[(row + grp + 8) * QP + kb + tig]);
            a[2] = __float_as_uint(sQ[(row + grp    ) * QP + kb + tig + 4]);
            a[3] = __float_as_uint(sQ[(row + grp + 8) * QP + kb + tig + 4]);
#pragma unroll
            for (int j = 0; j < 4; j++) {
                const int col = wn * 32 + j * 8;
                uint32_t bfr[2];
                bfr[0] = __float_as_uint(sK[(col + grp) * KP + kb + tig]);
                bfr[1] = __float_as_uint(sK[(col + grp) * KP + kb + tig + 4]);
                mma8(sf[j], a, bfr);
            }
        }

        // Causal mask + store S frags to smem
        {
            const int r1 = wm * 16 + grp, r2 = r1 + 8;
            if (kt == qt) {
#pragma unroll
                for (int j = 0; j < 4; j++) {
                    int col = wn * 32 + j * 8 + tig * 2;
                    int kc0 = k0 + col, kc1 = kc0 + 1;
                    sS[r1 * SP + col]     = (kc0 <= q0 + r1) ? sf[j][0] : -1e30f;
                    sS[r1 * SP + col + 1] = (kc1 <= q0 + r1) ? sf[j][1] : -1e30f;
                    sS[r2 * SP + col]     = (kc0 <= q0 + r2) ? sf[j][2] : -1e30f;
                    sS[r2 * SP + col + 1] = (kc1 <= q0 + r2) ? sf[j][3] : -1e30f;
                }
            } else {
#pragma unroll
                for (int j = 0; j < 4; j++) {
                    int col = wn * 32 + j * 8 + tig * 2;
                    sS[r1 * SP + col]     = sf[j][0];
                    sS[r1 * SP + col + 1] = sf[j][1];
                    sS[r2 * SP + col]     = sf[j][2];
                    sS[r2 * SP + col + 1] = sf[j][3];
                }
            }
        }
        __syncthreads();

        // Online softmax: 4 threads per row; P stored tf32-rounded
        {
            int r = tid >> 2, l4 = tid & 3;
            float* srow = sS + r * SP;
            float mx = -1e30f;
#pragma unroll
            for (int c = l4; c < 64; c += 4) mx = fmaxf(mx, srow[c]);
            mx = fmaxf(mx, __shfl_xor_sync(0xffffffffu, mx, 1));
            mx = fmaxf(mx, __shfl_xor_sync(0xffffffffu, mx, 2));
            float mold = sM[r];
            float mnew = fmaxf(mold, mx);
            float sum = 0.f;
#pragma unroll
            for (int c = l4; c < 64; c += 4) {
                float p = tf32r(__expf(srow[c] - mnew));
                srow[c] = p;
                sum += p;
            }
            sum += __shfl_xor_sync(0xffffffffu, sum, 1);
            sum += __shfl_xor_sync(0xffffffffu, sum, 2);
            if (l4 == 0) {
                sAl[r] = __expf(mold - mnew);
                sL[r]  = sL[r] * sAl[r] + sum;
                sM[r]  = mnew;
            }
        }
        __syncthreads();

        // Rescale O and accumulate P @ V via mma (8 k-steps of 8 over 64)
        {
            const int r1 = wm * 16 + grp, r2 = r1 + 8;
            float al1 = sAl[r1], al2 = sAl[r2];
#pragma unroll
            for (int j = 0; j < 8; j++) {
                of[j][0] *= al1; of[j][1] *= al1;
                of[j][2] *= al2; of[j][3] *= al2;
            }
        }
#pragma unroll
        for (int ks = 0; ks < 8; ks++) {
            const int kb = ks * 8;
            uint32_t a[4];
            const int row = wm * 16;
            a[0] = __float_as_uint(sS[(row + grp    ) * SP + kb + tig]);
            a[1] = __float_as_uint(sS[(row + grp + 8) * SP + kb + tig]);
            a[2] = __float_as_uint(sS[(row + grp    ) * SP + kb + tig + 4]);
            a[3] = __float_as_uint(sS[(row + grp + 8) * SP + kb + tig + 4]);
#pragma unroll
            for (int j = 0; j < 8; j++) {
                const int col = wn * 64 + j * 8;
                uint32_t bfr[2];
                bfr[0] = __float_as_uint(sVT[(col + grp) * VP + kb + tig]);
                bfr[1] = __float_as_uint(sVT[(col + grp) * VP + kb + tig + 4]);
                mma8(of[j], a, bfr);
            }
        }
    }

    // Epilogue: normalize and write
    {
        const int r1 = wm * 16 + grp, r2 = r1 + 8;
        float inv1 = 1.f / sL[r1], inv2 = 1.f / sL[r2];
        size_t base1 = (size_t)(rowb + q0 + r1) * D_ + h * HD_;
        size_t base2 = (size_t)(rowb + q0 + r2) * D_ + h * HD_;
#pragma unroll
        for (int j = 0; j < 8; j++) {
            int n = wn * 64 + j * 8 + tig * 2;
            *(float2*)&g_ao[base1 + n] = make_float2(of[j][0] * inv1, of[j][1] * inv1);
            *(float2*)&g_ao[base2 + n] = make_float2(of[j][2] * inv2, of[j][3] * inv2);
        }
    }
}

// ---------------------------------------------------------------------------
// Launch
// ---------------------------------------------------------------------------
extern "C" void kernel_launch(void* const* d_in, const int* in_sizes, int n_in,
                              void* d_out, int out_size) {
    const float* x    = (const float*)d_in[0];
    const float* wq   = (const float*)d_in[1];
    const float* wkvd = (const float*)d_in[2];
    const float* wkup = (const float*)d_in[3];
    const float* wkr  = (const float*)d_in[4];
    const float* wvup = (const float*)d_in[5];
    const float* wo   = (const float*)d_in[6];
    float* out = (float*)d_out;

    float *q_p, *ckv_p, *kn_p, *kr_p, *v_p, *ao_p;
    cudaGetSymbolAddress((void**)&q_p,   g_q);
    cudaGetSymbolAddress((void**)&ckv_p, g_ckv);
    cudaGetSymbolAddress((void**)&kn_p,  g_kn);
    cudaGetSymbolAddress((void**)&kr_p,  g_kr);
    cudaGetSymbolAddress((void**)&v_p,   g_v);
    cudaGetSymbolAddress((void**)&ao_p,  g_ao);

    cudaFuncSetAttribute(flash_kernel,
                         cudaFuncAttributeMaxDynamicSharedMemorySize,
                         FLASH_SMEM);

    build_rope_table<<<(S_ * 32 + 255) / 256, 256>>>();

    // Projections (all NT GEMMs, tf32 tensor cores)
    tgemm_nt<<<dim3(D_ / 128, M_ / 128), 256>>>(x, wq, q_p, M_, D_, D_);
    tgemm_nt<<<dim3(R_ / 128, M_ / 128), 256>>>(x, wkvd, ckv_p, M_, R_, D_);
    tgemm_nt<<<dim3((H_ * ND_) / 128, M_ / 128), 256>>>(ckv_p, wkup, kn_p, M_, H_ * ND_, R_);
    tgemm_nt<<<dim3(1, M_ / 128), 256>>>(x, wkr, kr_p, M_, ND_, D_);
    tgemm_nt<<<dim3(D_ / 128, M_ / 128), 256>>>(ckv_p, wvup, v_p, M_, D_, R_);

    // RoPE
    rope_q_kernel<<<(M_ * H_ * 32) / 256, 256>>>();
    rope_k_kernel<<<(M_ * 32) / 256, 256>>>();

    // Flash attention
    flash_kernel<<<dim3(S_ / 64, H_, B_), 256, FLASH_SMEM>>>();

    // Output projection
    tgemm_nt<<<dim3(D_ / 128, M_ / 128), 256>>>(ao_p, wo, out, M_, D_, D_);
}